// round 5
// baseline (speedup 1.0000x reference)
#include <cuda_runtime.h>

// B=4096, N=64, H=16, FALLBACK=12
// grid (B,1,64,64) f32 | hints (B,2,64,16) f32 | w_g (1,64,64) | w_h (2,64,16)

__device__ int g_ctr;

static __global__ void zero_kernel(float* out) { out[0] = 0.0f; g_ctr = 0; }

#define NB   4096
#define NCTA 592   // 4 CTAs/SM x 148 SMs: one persistent wave, work-stealing

__global__ void __launch_bounds__(256, 4) energy_kernel(
    const float* __restrict__ grid, const float* __restrict__ hints,
    const float* __restrict__ wg,   const float* __restrict__ wh,
    float* __restrict__ out)
{
    __shared__ float wgs[4096];     // w_g, 16KB
    __shared__ float whs[2048];     // w_h,  8KB
    __shared__ float hsum[128];     // row/col targets
    __shared__ float colp[1024];    // 16 rowgroups x 64 column partials
    __shared__ int   slast[2];
    __shared__ float wred[8];
    __shared__ int   snext;

    const int t  = threadIdx.x;
    const int rg = t >> 4;          // row-group 0..15
    const int c0 = (t & 15) << 2;   // owned column start
    const int p  = t >> 1;          // hint row (2 threads/row)

    const float4* grid4  = reinterpret_cast<const float4*>(grid);
    const float4* hints4 = reinterpret_cast<const float4*>(hints);

    if (t == 0) snext = atomicAdd(&g_ctr, 1);
    if (t < 2)  slast[t] = -1;

    // One-time weight preload into shared
    {
        const float4* wgv  = reinterpret_cast<const float4*>(wg);
        const float4* whv  = reinterpret_cast<const float4*>(wh);
        float4* wgs4w = reinterpret_cast<float4*>(wgs);
        float4* whs4w = reinterpret_cast<float4*>(whs);
        #pragma unroll
        for (int k = 0; k < 4; ++k) wgs4w[k * 256 + t] = wgv[k * 256 + t];
        #pragma unroll
        for (int k = 0; k < 2; ++k) whs4w[k * 256 + t] = whv[k * 256 + t];
    }
    __syncthreads();

    int b = snext;
    if (b >= NB) return;

    const float4* wgs4 = reinterpret_cast<const float4*>(wgs);
    const float4* whs4 = reinterpret_cast<const float4*>(whs);

    // Prologue prefetch of batch b into registers
    float4 G0, G1, G2, G3, H0, H1;
    {
        const float4* gb = grid4  + (size_t)b * 1024;
        const float4* hb = hints4 + (size_t)b * 512;
        G0 = gb[t]; G1 = gb[256 + t]; G2 = gb[512 + t]; G3 = gb[768 + t];
        H0 = hb[2 * t]; H1 = hb[2 * t + 1];
    }

    float acc = 0.0f;

    while (true) {
        // ---- Phase 1: hints from registers (no global loads); steal next ----
        if (t == 0) snext = atomicAdd(&g_ctr, 1);
        float s2p, hs;
        {
            float4 w0 = whs4[2 * t], w1 = whs4[2 * t + 1];
            hs  = (H0.x + H0.y) + (H0.z + H0.w) + (H1.x + H1.y) + (H1.z + H1.w);
            s2p = H0.x * w0.x + H0.y * w0.y + H0.z * w0.z + H0.w * w0.w
                + H1.x * w1.x + H1.y * w1.y + H1.z * w1.z + H1.w * w1.w;
        }
        float hsfull = hs + __shfl_xor_sync(0xffffffffu, hs, 1);
        if ((t & 1) == 0) {
            hsum[p] = hsfull;
            if (hsfull > 0.0f) atomicMax(&slast[p >> 6], p & 63);
        }
        __syncthreads();    // A: hsum/slast/snext visible

        int bn = snext;
        int size;
        {
            int lr = slast[0], lc = slast[1];
            size = (lr >= 0 && lc >= 0) ? (max(lr, lc) + 1) : 12;
        }

        // Prefetch next hints: H is free, latency hidden under all of phase 2
        if (bn < NB) {
            const float4* hb = hints4 + (size_t)bn * 512;
            H0 = hb[2 * t]; H1 = hb[2 * t + 1];
        }

        // ---- Phase 2: compute from G registers + shared weights ----
        float s1p = 0.0f, binp = 0.0f, rerrp = 0.0f;
        float pc0 = 0.0f, pc1 = 0.0f, pc2 = 0.0f, pc3 = 0.0f;

        if (size == 64) {   // dominant case: no masking anywhere
            #pragma unroll
            for (int k = 0; k < 4; ++k) {
                float4 g = (k == 0) ? G0 : (k == 1) ? G1 : (k == 2) ? G2 : G3;
                float4 w = wgs4[k * 256 + t];
                s1p  += g.x * w.x + g.y * w.y + g.z * w.z + g.w * w.w;
                binp += g.x * g.x + g.y * g.y + g.z * g.z + g.w * g.w;
                float s0 = __fdividef(1.0f, 1.0f + __expf(-3.0f * g.x));
                float s1 = __fdividef(1.0f, 1.0f + __expf(-3.0f * g.y));
                float s2 = __fdividef(1.0f, 1.0f + __expf(-3.0f * g.z));
                float s3 = __fdividef(1.0f, 1.0f + __expf(-3.0f * g.w));
                pc0 += s0; pc1 += s1; pc2 += s2; pc3 += s3;
                float pr = (s0 + s1) + (s2 + s3);
                pr += __shfl_xor_sync(0xffffffffu, pr, 1);
                pr += __shfl_xor_sync(0xffffffffu, pr, 2);
                pr += __shfl_xor_sync(0xffffffffu, pr, 4);
                pr += __shfl_xor_sync(0xffffffffu, pr, 8);
                if ((t & 15) == 0) {
                    float d = pr - hsum[k * 16 + rg];
                    rerrp += d * d;
                }
            }
        } else {            // generic masked path (rare)
            #pragma unroll
            for (int k = 0; k < 4; ++k) {
                int r = k * 16 + rg;
                float4 g = (k == 0) ? G0 : (k == 1) ? G1 : (k == 2) ? G2 : G3;
                float4 w = wgs4[k * 256 + t];
                s1p += g.x * w.x + g.y * w.y + g.z * w.z + g.w * w.w;

                float rm = (r < size) ? 1.0f : 0.0f;
                float gx[4] = {g.x, g.y, g.z, g.w};
                float sg[4], pr = 0.0f;
                #pragma unroll
                for (int e = 0; e < 4; ++e) {
                    float x = gx[e];
                    sg[e] = __fdividef(1.0f, 1.0f + __expf(-3.0f * x)) * rm;
                    if (c0 + e < size) {
                        pr   += sg[e];
                        binp += x * x * rm;
                    }
                }
                pc0 += sg[0]; pc1 += sg[1]; pc2 += sg[2]; pc3 += sg[3];

                pr += __shfl_xor_sync(0xffffffffu, pr, 1);
                pr += __shfl_xor_sync(0xffffffffu, pr, 2);
                pr += __shfl_xor_sync(0xffffffffu, pr, 4);
                pr += __shfl_xor_sync(0xffffffffu, pr, 8);
                if ((t & 15) == 0 && r < size) {
                    float d = pr - hsum[r];
                    rerrp += d * d;
                }
            }
        }
        *reinterpret_cast<float4*>(&colp[rg * 64 + c0]) =
            make_float4(pc0, pc1, pc2, pc3);
        __syncthreads();    // B: colp ready; all slast/hsum reads done

        if (t < 2) slast[t] = -1;   // reset for next batch

        // Prefetch next grid: G is free, latency hidden under phase 3 + phase 1
        if (bn < NB) {
            const float4* gb = grid4 + (size_t)bn * 1024;
            G0 = gb[t]; G1 = gb[256 + t]; G2 = gb[512 + t]; G3 = gb[768 + t];
        }

        // ---- Phase 3: column reduction + per-batch energy ----
        float cerrp = 0.0f;
        if (t < 64) {
            float ac = 0.0f;
            #pragma unroll
            for (int g2 = 0; g2 < 16; ++g2) ac += colp[g2 * 64 + t];
            if (t < size) {
                float d = ac - hsum[64 + t];
                cerrp = d * d;
            }
        }
        float inv = __fdividef(1.0f, (float)size);
        acc += s1p + s2p
             + 10.0f * inv * (rerrp + cerrp)
             + 0.1f  * inv * inv * binp;

        b = bn;
        if (b >= NB) break;
        __syncthreads();    // C: phase-3/colp reads done before next writes
    }

    // ---- Block reduction, one atomic per CTA ----
    #pragma unroll
    for (int o = 16; o > 0; o >>= 1)
        acc += __shfl_down_sync(0xffffffffu, acc, o);
    if ((t & 31) == 0) wred[t >> 5] = acc;
    __syncthreads();
    if (t < 32) {
        float v = (t < 8) ? wred[t] : 0.0f;
        #pragma unroll
        for (int o = 4; o > 0; o >>= 1)
            v += __shfl_down_sync(0xffffffffu, v, o);
        if (t == 0) atomicAdd(out, v * (1.0f / (float)NB));
    }
}

extern "C" void kernel_launch(void* const* d_in, const int* in_sizes, int n_in,
                              void* d_out, int out_size) {
    const float* grid  = (const float*)d_in[0];
    const float* hints = (const float*)d_in[1];
    const float* wg    = (const float*)d_in[2];
    const float* wh    = (const float*)d_in[3];
    float* out = (float*)d_out;

    zero_kernel<<<1, 1>>>(out);
    energy_kernel<<<NCTA, 256>>>(grid, hints, wg, wh, out);
}

// round 8
// speedup vs baseline: 1.0116x; 1.0116x over previous
#include <cuda_runtime.h>

// B=4096, N=64, H=16, FALLBACK=12
// grid (B,1,64,64) f32 | hints (B,2,64,16) f32 | w_g (1,64,64) | w_h (2,64,16)
// Design: one warp per batch, fully warp-synchronous (no in-loop __syncthreads).

static __global__ void zero_kernel(float* out) { out[0] = 0.0f; }

#define NCTA 512   // 512 CTAs x 8 warps = 4096 batches, one wave

__global__ void __launch_bounds__(256, 4) energy_kernel(
    const float* __restrict__ grid, const float* __restrict__ hints,
    const float* __restrict__ wg,   const float* __restrict__ wh,
    float* __restrict__ out)
{
    __shared__ float wgs[4096];      // w_g, 16KB, CTA-shared read-only
    __shared__ float whs[2048];      // w_h,  8KB
    __shared__ float tgt[8 * 128];   // per-warp: [0..63] row targets, [64..127] col targets
    __shared__ float wred[8];

    const int t   = threadIdx.x;
    const int wid = t >> 5;
    const int l   = t & 31;

    // One-time weight preload (only block-wide sync in the kernel body)
    {
        const float4* wgv = reinterpret_cast<const float4*>(wg);
        const float4* whv = reinterpret_cast<const float4*>(wh);
        float4* wgsw = reinterpret_cast<float4*>(wgs);
        float4* whsw = reinterpret_cast<float4*>(whs);
        #pragma unroll
        for (int k = 0; k < 4; ++k) wgsw[k * 256 + t] = wgv[k * 256 + t];
        #pragma unroll
        for (int k = 0; k < 2; ++k) whsw[k * 256 + t] = whv[k * 256 + t];
    }
    __syncthreads();

    const int b = blockIdx.x * 8 + wid;          // this warp's batch
    const float4* gb   = reinterpret_cast<const float4*>(grid)  + (size_t)b * 1024;
    const float4* hb   = reinterpret_cast<const float4*>(hints) + (size_t)b * 512;
    const float4* wgs4 = reinterpret_cast<const float4*>(wgs);
    const float4* whs4 = reinterpret_cast<const float4*>(whs);
    float* mytgt = &tgt[wid * 128];              // warp-private: no block sync needed

    // ---- Phase 1: hints (16 float4/lane, fully unrolled for MLP) ----
    float s2p = 0.0f;
    int lastr = -1, lastc = -1;
    #pragma unroll
    for (int k = 0; k < 16; ++k) {
        const int idx = k * 32 + l;              // float4 index, plane = k>>3
        float4 h = hb[idx];
        float4 w = whs4[idx];
        s2p += h.x * w.x + h.y * w.y + h.z * w.z + h.w * w.w;
        float part = (h.x + h.y) + (h.z + h.w);
        part += __shfl_xor_sync(0xffffffffu, part, 1);
        part += __shfl_xor_sync(0xffffffffu, part, 2);
        if ((l & 3) == 0) {                      // holds sum of 16 hint values
            const int hrow = (idx >> 2) & 63;
            mytgt[(k >> 3) * 64 + hrow] = part;
            if (part > 0.0f) {
                if ((k >> 3) == 0) lastr = max(lastr, hrow);
                else               lastc = max(lastc, hrow);
            }
        }
    }
    #pragma unroll
    for (int o = 16; o > 0; o >>= 1) {
        lastr = max(lastr, __shfl_xor_sync(0xffffffffu, lastr, o));
        lastc = max(lastc, __shfl_xor_sync(0xffffffffu, lastc, o));
    }
    const int size = (lastr >= 0 && lastc >= 0) ? (max(lastr, lastc) + 1) : 12;
    __syncwarp();                                 // mytgt visible to all lanes

    // ---- Phase 2: stream grid. lane owns columns c0..c0+3 for ALL rows ----
    const int c0    = (l & 15) << 2;
    const int rhalf = l >> 4;                     // row parity this lane sees
    float s1p = 0.0f, binp = 0.0f, rerrp = 0.0f;
    float pc0 = 0.0f, pc1 = 0.0f, pc2 = 0.0f, pc3 = 0.0f;

    if (size == 64) {                             // dominant unmasked path
        #pragma unroll 8
        for (int k = 0; k < 32; ++k) {
            const int idx = k * 32 + l;
            float4 g = gb[idx];
            float4 w = wgs4[idx];
            s1p  += g.x * w.x + g.y * w.y + g.z * w.z + g.w * w.w;
            binp += g.x * g.x + g.y * g.y + g.z * g.z + g.w * g.w;
            float s0 = __fdividef(1.0f, 1.0f + __expf(-3.0f * g.x));
            float s1 = __fdividef(1.0f, 1.0f + __expf(-3.0f * g.y));
            float s2 = __fdividef(1.0f, 1.0f + __expf(-3.0f * g.z));
            float s3 = __fdividef(1.0f, 1.0f + __expf(-3.0f * g.w));
            pc0 += s0; pc1 += s1; pc2 += s2; pc3 += s3;
            float pr = (s0 + s1) + (s2 + s3);
            pr += __shfl_xor_sync(0xffffffffu, pr, 1);
            pr += __shfl_xor_sync(0xffffffffu, pr, 2);
            pr += __shfl_xor_sync(0xffffffffu, pr, 4);
            pr += __shfl_xor_sync(0xffffffffu, pr, 8);
            if ((l & 15) == 0) {                  // lanes 0,16: rows 2k, 2k+1
                float d = pr - mytgt[2 * k + rhalf];
                rerrp += d * d;
            }
        }
    } else {                                      // generic masked path (rare)
        #pragma unroll 8
        for (int k = 0; k < 32; ++k) {
            const int idx = k * 32 + l;
            const int r   = 2 * k + rhalf;
            float4 g = gb[idx];
            float4 w = wgs4[idx];
            s1p += g.x * w.x + g.y * w.y + g.z * w.z + g.w * w.w;

            const float rm = (r < size) ? 1.0f : 0.0f;
            float gx[4] = {g.x, g.y, g.z, g.w};
            float sg[4], pr = 0.0f;
            #pragma unroll
            for (int e = 0; e < 4; ++e) {
                float x = gx[e];
                sg[e] = __fdividef(1.0f, 1.0f + __expf(-3.0f * x)) * rm;
                if (c0 + e < size) {
                    pr   += sg[e];
                    binp += x * x * rm;
                }
            }
            pc0 += sg[0]; pc1 += sg[1]; pc2 += sg[2]; pc3 += sg[3];

            pr += __shfl_xor_sync(0xffffffffu, pr, 1);
            pr += __shfl_xor_sync(0xffffffffu, pr, 2);
            pr += __shfl_xor_sync(0xffffffffu, pr, 4);
            pr += __shfl_xor_sync(0xffffffffu, pr, 8);
            if ((l & 15) == 0 && r < size) {
                float d = pr - mytgt[r];
                rerrp += d * d;
            }
        }
    }

    // ---- Phase 3: column sums — merge the two 16-lane halves, in registers ----
    pc0 += __shfl_xor_sync(0xffffffffu, pc0, 16);
    pc1 += __shfl_xor_sync(0xffffffffu, pc1, 16);
    pc2 += __shfl_xor_sync(0xffffffffu, pc2, 16);
    pc3 += __shfl_xor_sync(0xffffffffu, pc3, 16);
    float cerrp = 0.0f;
    if (l < 16) {                                 // avoid double count
        float pcs[4] = {pc0, pc1, pc2, pc3};
        #pragma unroll
        for (int e = 0; e < 4; ++e) {
            if (c0 + e < size) {
                float d = pcs[e] - mytgt[64 + c0 + e];
                cerrp += d * d;
            }
        }
    }

    // ---- Per-batch energy, warp reduce, CTA reduce, one atomic/CTA ----
    const float inv = __fdividef(1.0f, (float)size);
    float local = s1p + s2p
                + 10.0f * inv * (rerrp + cerrp)
                + 0.1f  * inv * inv * binp;
    #pragma unroll
    for (int o = 16; o > 0; o >>= 1)
        local += __shfl_down_sync(0xffffffffu, local, o);
    if (l == 0) wred[wid] = local;
    __syncthreads();
    if (t < 32) {
        float v = (l < 8) ? wred[l] : 0.0f;
        #pragma unroll
        for (int o = 4; o > 0; o >>= 1)
            v += __shfl_down_sync(0xffffffffu, v, o);
        if (l == 0) atomicAdd(out, v * (1.0f / 4096.0f));
    }
}

extern "C" void kernel_launch(void* const* d_in, const int* in_sizes, int n_in,
                              void* d_out, int out_size) {
    const float* grid  = (const float*)d_in[0];
    const float* hints = (const float*)d_in[1];
    const float* wg    = (const float*)d_in[2];
    const float* wh    = (const float*)d_in[3];
    float* out = (float*)d_out;

    zero_kernel<<<1, 1>>>(out);
    energy_kernel<<<NCTA, 256>>>(grid, hints, wg, wh, out);
}

// round 10
// speedup vs baseline: 1.1918x; 1.1781x over previous
#include <cuda_runtime.h>

// B=4096, N=64, H=16, FALLBACK=12
// grid (B,1,64,64) f32 | hints (B,2,64,16) f32 | w_g (1,64,64) | w_h (2,64,16)
// One warp per batch. 1024 CTAs x 128 thr (4 warps) for 1%-tail balance.
// Fast path uses sigmoid(3x)=0.5+0.5*tanh(1.5x): accumulate raw tanh sums,
// fold the affine into the error constants. Packed f32x2 FMAs via PTX.

static __global__ void zero_kernel(float* out) { out[0] = 0.0f; }

typedef unsigned long long u64;

__device__ __forceinline__ u64 pack2(float a, float b) {
    u64 r; asm("mov.b64 %0, {%1,%2};" : "=l"(r) : "f"(a), "f"(b)); return r;
}
__device__ __forceinline__ void unpack2(float& a, float& b, u64 v) {
    asm("mov.b64 {%0,%1}, %2;" : "=f"(a), "=f"(b) : "l"(v));
}
__device__ __forceinline__ void fma2(u64& d, u64 a, u64 b) {   // d += a*b (packed)
    asm("fma.rn.f32x2 %0, %1, %2, %0;" : "+l"(d) : "l"(a), "l"(b));
}
__device__ __forceinline__ u64 mul2(u64 a, u64 b) {
    u64 r; asm("mul.rn.f32x2 %0, %1, %2;" : "=l"(r) : "l"(a), "l"(b)); return r;
}
__device__ __forceinline__ void add2(u64& d, u64 a) {
    asm("add.rn.f32x2 %0, %1, %0;" : "+l"(d) : "l"(a));
}
__device__ __forceinline__ float tanhf_fast(float x) {
    float y; asm("tanh.approx.f32 %0, %1;" : "=f"(y) : "f"(x)); return y;
}

#define NCTA 1024

__global__ void __launch_bounds__(128, 8) energy_kernel(
    const float* __restrict__ grid, const float* __restrict__ hints,
    const float* __restrict__ wg,   const float* __restrict__ wh,
    float* __restrict__ out)
{
    __shared__ float wgs[4096];      // w_g 16KB
    __shared__ float whs[2048];      // w_h  8KB
    __shared__ float tgt[4 * 128];   // per-warp: [0..63] row tgts, [64..127] col tgts
    __shared__ float wred[4];

    const int t   = threadIdx.x;
    const int wid = t >> 5;
    const int l   = t & 31;

    // One-time weight preload
    {
        const float4* wgv = reinterpret_cast<const float4*>(wg);
        const float4* whv = reinterpret_cast<const float4*>(wh);
        float4* wgsw = reinterpret_cast<float4*>(wgs);
        float4* whsw = reinterpret_cast<float4*>(whs);
        #pragma unroll
        for (int k = 0; k < 8; ++k) wgsw[k * 128 + t] = wgv[k * 128 + t];
        #pragma unroll
        for (int k = 0; k < 4; ++k) whsw[k * 128 + t] = whv[k * 128 + t];
    }
    __syncthreads();

    const int b = blockIdx.x * 4 + wid;
    const float4* hb   = reinterpret_cast<const float4*>(hints) + (size_t)b * 512;
    const float4* whs4 = reinterpret_cast<const float4*>(whs);
    float* mytgt = &tgt[wid * 128];

    // ---- Phase 1: hints ----
    float s2p = 0.0f;
    int lastr = -1, lastc = -1;
    #pragma unroll
    for (int k = 0; k < 16; ++k) {
        const int idx = k * 32 + l;
        float4 h = hb[idx];
        float4 w = whs4[idx];
        s2p += h.x * w.x + h.y * w.y + h.z * w.z + h.w * w.w;
        float part = (h.x + h.y) + (h.z + h.w);
        part += __shfl_xor_sync(0xffffffffu, part, 1);
        part += __shfl_xor_sync(0xffffffffu, part, 2);
        if ((l & 3) == 0) {
            const int hrow = (idx >> 2) & 63;
            mytgt[(k >> 3) * 64 + hrow] = part;
            if (part > 0.0f) {
                if ((k >> 3) == 0) lastr = max(lastr, hrow);
                else               lastc = max(lastc, hrow);
            }
        }
    }
    #pragma unroll
    for (int o = 16; o > 0; o >>= 1) {
        lastr = max(lastr, __shfl_xor_sync(0xffffffffu, lastr, o));
        lastc = max(lastc, __shfl_xor_sync(0xffffffffu, lastc, o));
    }
    const int size = (lastr >= 0 && lastc >= 0) ? (max(lastr, lastc) + 1) : 12;
    __syncwarp();

    // ---- Phase 2 ----
    const int c0    = (l & 15) << 2;
    const int rhalf = l >> 4;
    const u64* gb2 = reinterpret_cast<const u64*>(grid) + (size_t)b * 2048;
    const u64* wg2 = reinterpret_cast<const u64*>(wgs);

    float s1p, binp, rerrp = 0.0f, cerrp = 0.0f;

    if (size == 64) {
        // -------- fast unmasked path: packed f32x2 + tanh algebra --------
        const u64 c15 = pack2(1.5f, 1.5f);
        u64 s1 = 0ull, bin = 0ull, pcA = 0ull, pcB = 0ull;  // packed accumulators
        #pragma unroll 8
        for (int k = 0; k < 32; ++k) {
            const int i2 = k * 64 + 2 * l;       // u64 index (two per float4)
            u64 g01 = gb2[i2],     g23 = gb2[i2 + 1];
            u64 w01 = wg2[i2],     w23 = wg2[i2 + 1];
            fma2(s1,  g01, w01);  fma2(s1,  g23, w23);
            fma2(bin, g01, g01);  fma2(bin, g23, g23);
            u64 a01 = mul2(g01, c15), a23 = mul2(g23, c15);
            float x0, x1, x2, x3;
            unpack2(x0, x1, a01); unpack2(x2, x3, a23);
            float t0 = tanhf_fast(x0), t1 = tanhf_fast(x1);
            float t2 = tanhf_fast(x2), t3 = tanhf_fast(x3);
            add2(pcA, pack2(t0, t1));
            add2(pcB, pack2(t2, t3));
            float tl = (t0 + t1) + (t2 + t3);    // lane's 4-col tanh sum, row 2k+rhalf
            tl += __shfl_xor_sync(0xffffffffu, tl, 1);
            tl += __shfl_xor_sync(0xffffffffu, tl, 2);
            tl += __shfl_xor_sync(0xffffffffu, tl, 4);
            tl += __shfl_xor_sync(0xffffffffu, tl, 8);
            if ((l & 15) == 0) {                 // row sum = 32 + 0.5*T
                float d = fmaf(0.5f, tl, 32.0f - mytgt[2 * k + rhalf]);
                rerrp += d * d;
            }
        }
        // horizontal finish
        float a, bq; unpack2(a, bq, s1);  s1p  = a + bq;
        unpack2(a, bq, bin);              binp = a + bq;
        float pc0, pc1, pc2, pc3;
        unpack2(pc0, pc1, pcA); unpack2(pc2, pc3, pcB);
        pc0 += __shfl_xor_sync(0xffffffffu, pc0, 16);
        pc1 += __shfl_xor_sync(0xffffffffu, pc1, 16);
        pc2 += __shfl_xor_sync(0xffffffffu, pc2, 16);
        pc3 += __shfl_xor_sync(0xffffffffu, pc3, 16);
        if (l < 16) {                            // col sum = 32 + 0.5*Tc
            float pcs[4] = {pc0, pc1, pc2, pc3};
            #pragma unroll
            for (int e = 0; e < 4; ++e) {
                float d = fmaf(0.5f, pcs[e], 32.0f - mytgt[64 + c0 + e]);
                cerrp += d * d;
            }
        }
    } else {
        // -------- generic masked path (rare): exact scalar sigmoid --------
        const float4* gb   = reinterpret_cast<const float4*>(grid) + (size_t)b * 1024;
        const float4* wgs4 = reinterpret_cast<const float4*>(wgs);
        s1p = 0.0f; binp = 0.0f;
        float pc0 = 0.0f, pc1 = 0.0f, pc2 = 0.0f, pc3 = 0.0f;
        #pragma unroll 8
        for (int k = 0; k < 32; ++k) {
            const int idx = k * 32 + l;
            const int r   = 2 * k + rhalf;
            float4 g = gb[idx];
            float4 w = wgs4[idx];
            s1p += g.x * w.x + g.y * w.y + g.z * w.z + g.w * w.w;
            const float rm = (r < size) ? 1.0f : 0.0f;
            float gx[4] = {g.x, g.y, g.z, g.w};
            float sg[4], pr = 0.0f;
            #pragma unroll
            for (int e = 0; e < 4; ++e) {
                float x = gx[e];
                sg[e] = __fdividef(1.0f, 1.0f + __expf(-3.0f * x)) * rm;
                if (c0 + e < size) {
                    pr   += sg[e];
                    binp += x * x * rm;
                }
            }
            pc0 += sg[0]; pc1 += sg[1]; pc2 += sg[2]; pc3 += sg[3];
            pr += __shfl_xor_sync(0xffffffffu, pr, 1);
            pr += __shfl_xor_sync(0xffffffffu, pr, 2);
            pr += __shfl_xor_sync(0xffffffffu, pr, 4);
            pr += __shfl_xor_sync(0xffffffffu, pr, 8);
            if ((l & 15) == 0 && r < size) {
                float d = pr - mytgt[r];
                rerrp += d * d;
            }
        }
        pc0 += __shfl_xor_sync(0xffffffffu, pc0, 16);
        pc1 += __shfl_xor_sync(0xffffffffu, pc1, 16);
        pc2 += __shfl_xor_sync(0xffffffffu, pc2, 16);
        pc3 += __shfl_xor_sync(0xffffffffu, pc3, 16);
        if (l < 16) {
            float pcs[4] = {pc0, pc1, pc2, pc3};
            #pragma unroll
            for (int e = 0; e < 4; ++e) {
                if (c0 + e < size) {
                    float d = pcs[e] - mytgt[64 + c0 + e];
                    cerrp += d * d;
                }
            }
        }
    }

    // ---- Per-batch energy, warp reduce, CTA reduce, one atomic/CTA ----
    const float inv = __fdividef(1.0f, (float)size);
    float local = s1p + s2p
                + 10.0f * inv * (rerrp + cerrp)
                + 0.1f  * inv * inv * binp;
    #pragma unroll
    for (int o = 16; o > 0; o >>= 1)
        local += __shfl_down_sync(0xffffffffu, local, o);
    if (l == 0) wred[wid] = local;
    __syncthreads();
    if (t < 32) {
        float v = (l < 4) ? wred[l] : 0.0f;
        v += __shfl_down_sync(0xffffffffu, v, 2);
        v += __shfl_down_sync(0xffffffffu, v, 1);
        if (l == 0) atomicAdd(out, v * (1.0f / 4096.0f));
    }
}

extern "C" void kernel_launch(void* const* d_in, const int* in_sizes, int n_in,
                              void* d_out, int out_size) {
    const float* grid  = (const float*)d_in[0];
    const float* hints = (const float*)d_in[1];
    const float* wg    = (const float*)d_in[2];
    const float* wh    = (const float*)d_in[3];
    float* out = (float*)d_out;

    zero_kernel<<<1, 1>>>(out);
    energy_kernel<<<NCTA, 128>>>(grid, hints, wg, wh, out);
}